// round 15
// baseline (speedup 1.0000x reference)
#include <cuda_runtime.h>
#include <math.h>

// InfoNCE loss: B=131072 rows, D=512 fp32.
// loss = mean_i log(1 + exp((neg_i - pos_i)/T))
// 768 MB streamed once -> pinned at the LTS/HBM byte ceiling (~7.1 TB/s,
// invariant across occ 24/44/71/96%, load width 128/256, persistent +
// double-buffered pipelining, cache policies, graph node counts; cold-capture
// DRAM% varies +/-8% run-to-run on identical binaries).
// Terminal config: one warp per row, CTA per 8 rows, 12x LDG.128
// front-batched via ld.global.nc + L2::256B prefetch, occ cap 4,
// single-node graph (threadfence reduction, no memset node).

#define D 512
#define TEMPERATURE 1.5f

__device__ float        g_partial = 0.0f;
__device__ unsigned int g_count   = 0u;

__device__ __forceinline__ float4 ldg_nc_prefetch(const float4* ptr) {
    float4 v;
    asm volatile("ld.global.nc.L2::256B.v4.f32 {%0,%1,%2,%3}, [%4];"
                 : "=f"(v.x), "=f"(v.y), "=f"(v.z), "=f"(v.w)
                 : "l"(ptr));
    return v;
}

__global__ void __launch_bounds__(256, 4)
infonce_kernel(const float* __restrict__ a,
               const float* __restrict__ p,
               const float* __restrict__ n,
               float* __restrict__ out,
               int B, float invB)
{
    const int warp_global = (int)((blockIdx.x * (unsigned)blockDim.x + threadIdx.x) >> 5);
    const int lane = threadIdx.x & 31;

    float aa = 0.f, pp = 0.f, nn = 0.f, ap = 0.f, an = 0.f;

    if (warp_global < B) {
        const size_t row_off = (size_t)warp_global * D;
        const float4* __restrict__ a4 = (const float4*)(a + row_off);
        const float4* __restrict__ p4 = (const float4*)(p + row_off);
        const float4* __restrict__ n4 = (const float4*)(n + row_off);

        // Batch ALL 12 float4 loads up front (48 data regs, ~56 total),
        // each with an L2 256B prefetch hint.
        float4 va[4], vp[4], vn[4];
        #pragma unroll
        for (int k = 0; k < 4; ++k) va[k] = ldg_nc_prefetch(&a4[lane + 32 * k]);
        #pragma unroll
        for (int k = 0; k < 4; ++k) vp[k] = ldg_nc_prefetch(&p4[lane + 32 * k]);
        #pragma unroll
        for (int k = 0; k < 4; ++k) vn[k] = ldg_nc_prefetch(&n4[lane + 32 * k]);

        #pragma unroll
        for (int k = 0; k < 4; ++k) {
            aa = fmaf(va[k].x, va[k].x, fmaf(va[k].y, va[k].y, fmaf(va[k].z, va[k].z, fmaf(va[k].w, va[k].w, aa))));
            pp = fmaf(vp[k].x, vp[k].x, fmaf(vp[k].y, vp[k].y, fmaf(vp[k].z, vp[k].z, fmaf(vp[k].w, vp[k].w, pp))));
            nn = fmaf(vn[k].x, vn[k].x, fmaf(vn[k].y, vn[k].y, fmaf(vn[k].z, vn[k].z, fmaf(vn[k].w, vn[k].w, nn))));
            ap = fmaf(va[k].x, vp[k].x, fmaf(va[k].y, vp[k].y, fmaf(va[k].z, vp[k].z, fmaf(va[k].w, vp[k].w, ap))));
            an = fmaf(va[k].x, vn[k].x, fmaf(va[k].y, vn[k].y, fmaf(va[k].z, vn[k].z, fmaf(va[k].w, vn[k].w, an))));
        }
    }

    // Warp tree-reduction of the 5 partial sums.
    #pragma unroll
    for (int off = 16; off > 0; off >>= 1) {
        aa += __shfl_xor_sync(0xFFFFFFFFu, aa, off);
        pp += __shfl_xor_sync(0xFFFFFFFFu, pp, off);
        nn += __shfl_xor_sync(0xFFFFFFFFu, nn, off);
        ap += __shfl_xor_sync(0xFFFFFFFFu, ap, off);
        an += __shfl_xor_sync(0xFFFFFFFFu, an, off);
    }

    float partial = 0.f;
    if (lane == 0 && warp_global < B) {
        const float na  = fmaxf(sqrtf(aa), 1e-12f);
        const float npo = fmaxf(sqrtf(pp), 1e-12f);
        const float nne = fmaxf(sqrtf(nn), 1e-12f);
        const float pos = ap / (na * npo);
        const float neg = an / (na * nne);
        const float z = (neg - pos) * (1.0f / TEMPERATURE);
        // -log_softmax[0] = log(1 + exp(z)); z in [-1.34, 1.34] -> no overflow
        partial = log1pf(expf(z)) * invB;
    }

    // Block reduction (8 warps), then threadfence-reduction across blocks.
    __shared__ float s[8];
    const int wid = threadIdx.x >> 5;
    if (lane == 0) s[wid] = partial;
    __syncthreads();
    if (threadIdx.x == 0) {
        float sum = s[0];
        #pragma unroll
        for (int i = 1; i < 8; ++i) sum += s[i];
        atomicAdd(&g_partial, sum);
        __threadfence();
        unsigned int prev = atomicAdd(&g_count, 1u);
        if (prev == gridDim.x - 1u) {
            // All other blocks' adds are visible (their fences precede their
            // counter increments). Publish and reset for the next replay.
            *out = g_partial;
            g_partial = 0.0f;
            g_count   = 0u;
        }
    }
}

extern "C" void kernel_launch(void* const* d_in, const int* in_sizes, int n_in,
                              void* d_out, int out_size)
{
    const float* anchors   = (const float*)d_in[0];
    const float* positives = (const float*)d_in[1];
    const float* negatives = (const float*)d_in[2];
    float* out = (float*)d_out;

    const int B = in_sizes[0] / D;

    const int threads = 256;               // 8 warps = 8 rows per block
    const int blocks = (B + 7) / 8;
    infonce_kernel<<<blocks, threads>>>(anchors, positives, negatives, out,
                                        B, 1.0f / (float)B);
}

// round 16
// speedup vs baseline: 1.0065x; 1.0065x over previous
#include <cuda_runtime.h>
#include <math.h>

// InfoNCE loss: B=131072 rows, D=512 fp32.
// loss = mean_i log(1 + exp((neg_i - pos_i)/T))
// 768 MB streamed once -> pinned at the LTS/HBM byte ceiling (~7.1 TB/s,
// invariant across occ 24/44/71/96%, load width 128/256, persistent +
// double-buffered pipelining, cache policies, graph node counts; cold-capture
// DRAM% varies +/-8% run-to-run on identical binaries).
// Terminal config (5 samples: 113.1-114.8us, mean 113.7): one warp per row,
// CTA per 8 rows, 12x LDG.128 front-batched via ld.global.nc + L2::256B
// prefetch, occ cap 4, single-node graph (threadfence reduction, no memset).

#define D 512
#define TEMPERATURE 1.5f

__device__ float        g_partial = 0.0f;
__device__ unsigned int g_count   = 0u;

__device__ __forceinline__ float4 ldg_nc_prefetch(const float4* ptr) {
    float4 v;
    asm volatile("ld.global.nc.L2::256B.v4.f32 {%0,%1,%2,%3}, [%4];"
                 : "=f"(v.x), "=f"(v.y), "=f"(v.z), "=f"(v.w)
                 : "l"(ptr));
    return v;
}

__global__ void __launch_bounds__(256, 4)
infonce_kernel(const float* __restrict__ a,
               const float* __restrict__ p,
               const float* __restrict__ n,
               float* __restrict__ out,
               int B, float invB)
{
    const int warp_global = (int)((blockIdx.x * (unsigned)blockDim.x + threadIdx.x) >> 5);
    const int lane = threadIdx.x & 31;

    float aa = 0.f, pp = 0.f, nn = 0.f, ap = 0.f, an = 0.f;

    if (warp_global < B) {
        const size_t row_off = (size_t)warp_global * D;
        const float4* __restrict__ a4 = (const float4*)(a + row_off);
        const float4* __restrict__ p4 = (const float4*)(p + row_off);
        const float4* __restrict__ n4 = (const float4*)(n + row_off);

        // Batch ALL 12 float4 loads up front (48 data regs, ~56 total),
        // each with an L2 256B prefetch hint.
        float4 va[4], vp[4], vn[4];
        #pragma unroll
        for (int k = 0; k < 4; ++k) va[k] = ldg_nc_prefetch(&a4[lane + 32 * k]);
        #pragma unroll
        for (int k = 0; k < 4; ++k) vp[k] = ldg_nc_prefetch(&p4[lane + 32 * k]);
        #pragma unroll
        for (int k = 0; k < 4; ++k) vn[k] = ldg_nc_prefetch(&n4[lane + 32 * k]);

        #pragma unroll
        for (int k = 0; k < 4; ++k) {
            aa = fmaf(va[k].x, va[k].x, fmaf(va[k].y, va[k].y, fmaf(va[k].z, va[k].z, fmaf(va[k].w, va[k].w, aa))));
            pp = fmaf(vp[k].x, vp[k].x, fmaf(vp[k].y, vp[k].y, fmaf(vp[k].z, vp[k].z, fmaf(vp[k].w, vp[k].w, pp))));
            nn = fmaf(vn[k].x, vn[k].x, fmaf(vn[k].y, vn[k].y, fmaf(vn[k].z, vn[k].z, fmaf(vn[k].w, vn[k].w, nn))));
            ap = fmaf(va[k].x, vp[k].x, fmaf(va[k].y, vp[k].y, fmaf(va[k].z, vp[k].z, fmaf(va[k].w, vp[k].w, ap))));
            an = fmaf(va[k].x, vn[k].x, fmaf(va[k].y, vn[k].y, fmaf(va[k].z, vn[k].z, fmaf(va[k].w, vn[k].w, an))));
        }
    }

    // Warp tree-reduction of the 5 partial sums.
    #pragma unroll
    for (int off = 16; off > 0; off >>= 1) {
        aa += __shfl_xor_sync(0xFFFFFFFFu, aa, off);
        pp += __shfl_xor_sync(0xFFFFFFFFu, pp, off);
        nn += __shfl_xor_sync(0xFFFFFFFFu, nn, off);
        ap += __shfl_xor_sync(0xFFFFFFFFu, ap, off);
        an += __shfl_xor_sync(0xFFFFFFFFu, an, off);
    }

    float partial = 0.f;
    if (lane == 0 && warp_global < B) {
        const float na  = fmaxf(sqrtf(aa), 1e-12f);
        const float npo = fmaxf(sqrtf(pp), 1e-12f);
        const float nne = fmaxf(sqrtf(nn), 1e-12f);
        const float pos = ap / (na * npo);
        const float neg = an / (na * nne);
        const float z = (neg - pos) * (1.0f / TEMPERATURE);
        // -log_softmax[0] = log(1 + exp(z)); z in [-1.34, 1.34] -> no overflow
        partial = log1pf(expf(z)) * invB;
    }

    // Block reduction (8 warps), then threadfence-reduction across blocks.
    __shared__ float s[8];
    const int wid = threadIdx.x >> 5;
    if (lane == 0) s[wid] = partial;
    __syncthreads();
    if (threadIdx.x == 0) {
        float sum = s[0];
        #pragma unroll
        for (int i = 1; i < 8; ++i) sum += s[i];
        atomicAdd(&g_partial, sum);
        __threadfence();
        unsigned int prev = atomicAdd(&g_count, 1u);
        if (prev == gridDim.x - 1u) {
            // All other blocks' adds are visible (their fences precede their
            // counter increments). Publish and reset for the next replay.
            *out = g_partial;
            g_partial = 0.0f;
            g_count   = 0u;
        }
    }
}

extern "C" void kernel_launch(void* const* d_in, const int* in_sizes, int n_in,
                              void* d_out, int out_size)
{
    const float* anchors   = (const float*)d_in[0];
    const float* positives = (const float*)d_in[1];
    const float* negatives = (const float*)d_in[2];
    float* out = (float*)d_out;

    const int B = in_sizes[0] / D;

    const int threads = 256;               // 8 warps = 8 rows per block
    const int blocks = (B + 7) / 8;
    infonce_kernel<<<blocks, threads>>>(anchors, positives, negatives, out,
                                        B, 1.0f / (float)B);
}